// round 7
// baseline (speedup 1.0000x reference)
#include <cuda_runtime.h>

#define BSZ  512
#define NN   128
#define NMAT 2560
#define SS   132             // stage row stride (words): 132 ≡ 4 (mod 32)

__device__ __forceinline__ float frcp(float x) {
    float r;
    asm("rcp.approx.ftz.f32 %0, %1;" : "=f"(r) : "f"(x));
    return r;
}
__device__ __forceinline__ void barn(int id, int cnt) {
    asm volatile("bar.sync %0, %1;" :: "r"(id), "r"(cnt) : "memory");
}

// ---------------- persistent scratch (__device__ globals) -------------------
__device__ float g_Ts[128];
__device__ int   g_perm[128];
__device__ float g_A [129 * 128];
__device__ float g_Cc[129 * 128];
__device__ int   g_kidx[BSZ * NN];

// ---------------- kernel 1: rank thresholds ---------------------------------
__global__ void k_rank(const float* __restrict__ w1, const float* __restrict__ b1)
{
    __shared__ float tsh[128];
    int l = threadIdx.x;
    float w  = w1[l];
    float bb = b1[l];
    float tv;
    if (w != 0.0f) tv = -bb / w;
    else           tv = (bb > 0.0f) ? -3.0e38f : 3.0e38f;
    tsh[l] = tv;
    __syncthreads();
    int r = 0;
    for (int p = 0; p < 128; ++p) {
        float o = tsh[p];
        r += (o < tv) || (o == tv && p < l);
    }
    g_Ts[r]   = tv;
    g_perm[r] = l;
}

// ---------------- kernel 2: interval tables ---------------------------------
__global__ void k_tables(const float* __restrict__ w1, const float* __restrict__ b1,
                         const float* __restrict__ w2, const float* __restrict__ b2)
{
    __shared__ float ws[128], bs[128];
    __shared__ int   ps[128];
    int k = blockIdx.x;       // 0..128
    int j = threadIdx.x;      // 0..127
    ps[j] = g_perm[j];
    __syncthreads();
    ws[j] = w1[ps[j]];
    bs[j] = b1[ps[j]];
    __syncthreads();
    float a = 0.f, c = 0.f;
    #pragma unroll 4
    for (int p = 0; p < 128; ++p) {
        float w  = ws[p];
        float bb = bs[p];
        bool pos = (w > 0.f) || (w == 0.f && bb > 0.f);
        bool act = pos ? (p < k) : (p >= k);
        if (act) {
            float wv = w2[j * 128 + ps[p]];
            a = fmaf(w,  wv, a);
            c = fmaf(bb, wv, c);
        }
    }
    g_A [k * 128 + j] = a;
    g_Cc[k * 128 + j] = c + b2[j];
}

// ---------------- kernel 3: interval index per scalar -----------------------
__global__ void k_kidx(const float* __restrict__ x)
{
    int i = blockIdx.x * blockDim.x + threadIdx.x;
    if (i >= BSZ * NN) return;
    float xv = x[i];
    int lo = 0, hi = 128;
    while (lo < hi) {
        int mid = (lo + hi) >> 1;
        if (g_Ts[mid] < xv) lo = mid + 1; else hi = mid;
    }
    g_kidx[i] = lo;
}

// ---------------- kernel 4: register-resident evolving Sinkhorn -------------
// warp w: g=w>>2 (row group), q=w&3 (column quarter); lane -> row r=32g+lane.
// Slice columns are PERMUTED: af[cb+j] = M[r][32q + cb + (j^msw)],
// msw=(lane>>1)&12, so butterfly stages off=16/off=8 are select-free.
// Sync: per-iteration only 2 NAMED barriers (128 threads each):
//   bar(1+g): row partials P1 ready (group-local)
//   bar(5+q): col partials P2 ready (quarter-local)
// P1/P2 double-buffered on iteration parity (WAR across decoupled groups).
__global__ __launch_bounds__(512, 2) void k_sinkhorn(
    const float* __restrict__ x,
    const float* __restrict__ noise,
    float* __restrict__ out)
{
    extern __shared__ float sm[];
    float* stage = sm;                    // [128][SS]
    float* P1    = sm + 128 * SS;         // [2][128*5]
    float* P2    = P1 + 2 * 128 * 5;      // [2][4][SS]
    float* CvW   = P2 + 2 * 4 * SS;       // [16][32] per-warp C copies
    float* xs    = CvW + 16 * 32;         // [128]
    int*   ks    = (int*)(xs + 128);      // [128]

    const int m    = blockIdx.x;
    const int b    = m & (BSZ - 1);
    const int tid  = threadIdx.x;
    const int lane = tid & 31;
    const int wrp  = tid >> 5;
    const int g    = wrp >> 2;
    const int q    = wrp & 3;
    const int r    = 32 * g + lane;
    const int msw  = (lane >> 1) & 12;

    if (tid < 128) {
        xs[tid] = x[b * NN + tid];
        ks[tid] = g_kidx[b * NN + tid];
    }
    __syncthreads();

    // ---- prologue: build M0 into stage[row][col], fully coalesced ----------
    const float* nzm = noise + (size_t)m * (NN * NN);
    #pragma unroll
    for (int h = 0; h < 8; ++h) {
        int id  = h * 512 + tid;          // float4 index; row uniform per warp
        int row = id >> 5;
        int c4  = (id & 31) * 4;
        int   kr = ks[row];
        float xv = xs[row];
        float4 a4 = *(const float4*)(g_A  + kr * 128 + c4);
        float4 q4 = *(const float4*)(g_Cc + kr * 128 + c4);
        float4 n4 = *(const float4*)(nzm + id * 4);
        float4 e;
        e.x = __expf(fmaf(a4.x, xv, q4.x) + n4.x);
        e.y = __expf(fmaf(a4.y, xv, q4.y) + n4.y);
        e.z = __expf(fmaf(a4.z, xv, q4.z) + n4.z);
        e.w = __expf(fmaf(a4.w, xv, q4.w) + n4.w);
        *(float4*)(stage + row * SS + c4) = e;
    }
    __syncthreads();

    // ---- pick up permuted row slice into registers -------------------------
    float4 rr[8];
    float* af = (float*)rr;
    #pragma unroll
    for (int t = 0; t < 8; ++t)
        rr[t] = *(const float4*)(stage + r * SS + 32 * q + ((4 * t) ^ msw));

    // ---- 10 evolving-Sinkhorn iterations -----------------------------------
    #pragma unroll 2
    for (int it = 0; it < 10; ++it) {
        float* P1b = P1 + (it & 1) * (128 * 5);
        float* P2b = P2 + (it & 1) * (4 * SS);

        // (1) row sum (float4 tree) -> group-local partial
        float4 t0 = make_float4(rr[0].x + rr[4].x, rr[0].y + rr[4].y,
                                rr[0].z + rr[4].z, rr[0].w + rr[4].w);
        float4 t1 = make_float4(rr[1].x + rr[5].x, rr[1].y + rr[5].y,
                                rr[1].z + rr[5].z, rr[1].w + rr[5].w);
        float4 t2 = make_float4(rr[2].x + rr[6].x, rr[2].y + rr[6].y,
                                rr[2].z + rr[6].z, rr[2].w + rr[6].w);
        float4 t3 = make_float4(rr[3].x + rr[7].x, rr[3].y + rr[7].y,
                                rr[3].z + rr[7].z, rr[3].w + rr[7].w);
        t0.x += t2.x; t0.y += t2.y; t0.z += t2.z; t0.w += t2.w;
        t1.x += t3.x; t1.y += t3.y; t1.z += t3.z; t1.w += t3.w;
        t0.x += t1.x; t0.y += t1.y; t0.z += t1.z; t0.w += t1.w;
        P1b[r * 5 + q] = (t0.x + t0.y) + (t0.z + t0.w);
        barn(1 + g, 128);

        // (2) re-derive R per thread; scale rows in place
        float rs = (P1b[r * 5 + 0] + P1b[r * 5 + 1]) +
                   (P1b[r * 5 + 2] + P1b[r * 5 + 3]);
        float R_own = frcp(rs);
        #pragma unroll
        for (int k = 0; k < 8; ++k) {
            rr[k].x *= R_own; rr[k].y *= R_own;
            rr[k].z *= R_own; rr[k].w *= R_own;
        }

        // (3) column sums: two select-light butterfly passes over warp rows
        #pragma unroll
        for (int pass = 0; pass < 2; ++pass) {
            const int cb = 16 * pass;
            float w8[8];
            #pragma unroll
            for (int j = 0; j < 8; ++j)     // col bit3 <- lane bit4 (pre-swizzled)
                w8[j] = af[cb + j] +
                        __shfl_xor_sync(0xffffffffu, af[cb + j + 8], 16);
            float w4[4];
            #pragma unroll
            for (int j = 0; j < 4; ++j)     // col bit2 <- lane bit3 (pre-swizzled)
                w4[j] = w8[j] + __shfl_xor_sync(0xffffffffu, w8[j + 4], 8);
            float w2v[2];
            bool u4 = (lane & 4) != 0;      // col bit1 <- lane bit2 (select)
            #pragma unroll
            for (int j = 0; j < 2; ++j) {
                float sd = u4 ? w4[j] : w4[j + 2];
                float kp = u4 ? w4[j + 2] : w4[j];
                w2v[j] = kp + __shfl_xor_sync(0xffffffffu, sd, 4);
            }
            bool u2b = (lane & 2) != 0;     // col bit0 <- lane bit1 (select)
            float sd = u2b ? w2v[0] : w2v[1];
            float kp = u2b ? w2v[1] : w2v[0];
            float w1 = kp + __shfl_xor_sync(0xffffffffu, sd, 2);
            float v  = w1 + __shfl_xor_sync(0xffffffffu, w1, 1);  // rows: bit0
            if (!(lane & 1))
                P2b[g * SS + 32 * q + cb + ((lane >> 1) & 15)] = v;
        }
        barn(5 + q, 128);

        // (4) per-warp C for own quarter (redundant across the 4 g-warps)
        {
            int cidx = 32 * q + lane;
            float cs = (P2b[cidx] + P2b[SS + cidx]) +
                       (P2b[2 * SS + cidx] + P2b[3 * SS + cidx]);
            CvW[wrp * 32 + lane] = frcp(cs);
        }
        __syncwarp();

        // (5) scale columns in place (swizzle-aligned vec4 broadcast)
        #pragma unroll
        for (int t = 0; t < 8; ++t) {
            float4 c4 = *(const float4*)(CvW + wrp * 32 + ((4 * t) ^ msw));
            rr[t].x *= c4.x; rr[t].y *= c4.y;
            rr[t].z *= c4.z; rr[t].w *= c4.w;
        }
    }

    // ---- epilogue: registers hold final M; transpose via stage -------------
    #pragma unroll
    for (int t = 0; t < 8; ++t) {
        int col = 32 * q + ((4 * t) ^ msw);
        stage[(col + 0) * SS + r] = rr[t].x;
        stage[(col + 1) * SS + r] = rr[t].y;
        stage[(col + 2) * SS + r] = rr[t].z;
        stage[(col + 3) * SS + r] = rr[t].w;
    }
    __syncthreads();
    float* om = out + (size_t)m * (NN * NN);
    #pragma unroll
    for (int h = 0; h < 8; ++h) {
        int id  = h * 512 + tid;
        int row = id >> 5;
        int c4  = (id & 31) * 4;
        *(float4*)(om + id * 4) = *(const float4*)(stage + row * SS + c4);
    }
}

// ---------------- launch ----------------------------------------------------
extern "C" void kernel_launch(void* const* d_in, const int* in_sizes, int n_in,
                              void* d_out, int out_size)
{
    const float* x     = (const float*)d_in[0];
    const float* w1    = (const float*)d_in[1];
    const float* b1    = (const float*)d_in[2];
    const float* w2    = (const float*)d_in[3];
    const float* b2    = (const float*)d_in[4];
    const float* noise = (const float*)d_in[5];
    float* out = (float*)d_out;

    k_rank  <<<1,   128>>>(w1, b1);
    k_tables<<<129, 128>>>(w1, b1, w2, b2);
    k_kidx  <<<256, 256>>>(x);

    // stage + P1(x2) + P2(x2) + CvW + xs + ks
    const int smem_words = 128 * SS + 2 * 128 * 5 + 2 * 4 * SS
                         + 16 * 32 + 128 + 128;
    const int smem_bytes = smem_words * 4;               // 80,000 B
    cudaFuncSetAttribute(k_sinkhorn, cudaFuncAttributeMaxDynamicSharedMemorySize,
                         smem_bytes);
    k_sinkhorn<<<NMAT, 512, smem_bytes>>>(x, noise, out);
}